// round 8
// baseline (speedup 1.0000x reference)
#include <cuda_runtime.h>
#include <cuda_bf16.h>
#include <cstdint>
#include <cstdio>

#define Bz   512
#define Wz   50
#define Tz   50
#define Hz   1024
#define Vz   1024
#define MVz  64
#define Lz   30
#define H4z  4096
#define SOSI 0
#define EOSI 1

// ===================== PTX helpers (base sm_103 ISA only) ===================
__device__ __forceinline__ uint32_t smem_u32(const void* p) {
    uint32_t a;
    asm("{ .reg .u64 t; cvta.to.shared.u64 t, %1; cvt.u32.u64 %0, t; }" : "=r"(a) : "l"(p));
    return a;
}
#define MBARRIER_INIT(addr, cnt) \
    asm volatile("mbarrier.init.shared.b64 [%0], %1;" :: "r"((uint32_t)(addr)), "r"((uint32_t)(cnt)) : "memory")
#define MBAR_WAIT(addr, parity) do {                                              \
    uint32_t _mb = (uint32_t)(addr); uint32_t _pp = (uint32_t)(parity);           \
    uint32_t _done;                                                               \
    asm volatile("{\n\t.reg .pred p;\n\t"                                         \
        "mbarrier.try_wait.parity.acquire.cta.shared::cta.b64 p, [%1], %2;\n\t"   \
        "selp.b32 %0, 1, 0, p;\n\t}" : "=r"(_done) : "r"(_mb), "r"(_pp) : "memory"); \
    if (!_done) {                                                                 \
        asm volatile("{\n\t.reg .pred P1;\n\t"                                    \
            "WL_%=:\n\t"                                                          \
            "mbarrier.try_wait.parity.acquire.cta.shared::cta.b64 P1, [%0], %1, 0x989680;\n\t" \
            "@P1 bra.uni WD_%=;\n\t"                                              \
            "bra.uni WL_%=;\n\t"                                                  \
            "WD_%=:\n\t}" :: "r"(_mb), "r"(_pp) : "memory");                      \
    }                                                                             \
} while (0)

__device__ __forceinline__ void bulkcp(uint32_t dst, const void* src, uint32_t mbar) {
    asm volatile("cp.async.bulk.shared::cluster.global.mbarrier::complete_tx::bytes [%0], [%1], %2, [%3];"
        :: "r"(dst), "l"(src), "r"(16384u), "r"(mbar) : "memory");
}
__device__ __forceinline__ void ldsm_x4(uint32_t* r, uint32_t addr) {
    asm volatile("ldmatrix.sync.aligned.m8n8.x4.shared.b16 {%0,%1,%2,%3}, [%4];"
                 : "=r"(r[0]), "=r"(r[1]), "=r"(r[2]), "=r"(r[3]) : "r"(addr));
}
__device__ __forceinline__ void mma_bf16(float* c, const uint32_t* a, uint32_t b0, uint32_t b1) {
    asm volatile("mma.sync.aligned.m16n8k16.row.col.f32.bf16.bf16.f32 "
                 "{%0,%1,%2,%3}, {%4,%5,%6,%7}, {%8,%9}, {%0,%1,%2,%3};"
                 : "+f"(c[0]), "+f"(c[1]), "+f"(c[2]), "+f"(c[3])
                 : "r"(a[0]), "r"(a[1]), "r"(a[2]), "r"(a[3]), "r"(b0), "r"(b1));
}

// ===================== blocked (tile-image) layout ==========================
// Matrix R x K (bf16) stored as 16KB blocks of 128 rows x 64 cols with the
// ldmatrix XOR swizzle pre-applied (verbatim smem tile image).
__device__ __forceinline__ size_t blk_idx(int r, int k, int K) {
    const int rt = r >> 7, kc = k >> 6;
    const int rr = r & 127, kk = k & 63;
    const int gs = (kk >> 3) ^ (rr & 7);
    return ((size_t)(rt * (K >> 6) + kc) << 13) + rr * 64 + gs * 8 + (kk & 7);
}

// ===================== scratch (device globals) =============================
__device__ float g_h[Bz * Hz];
__device__ float g_c[Bz * Hz];
__device__ float g_aw[Bz * Wz];
__device__ float g_mmask[Lz * Bz];
__device__ float g_m[Bz];
__device__ float g_hb_enc[H4z];
__device__ float g_xb_gen[H4z];
__device__ float g_s0;
__device__ float g_gb_set[H4z], g_gb_gen[H4z], g_gb_menc[H4z], g_gb_dec[H4z];

__device__ __align__(1024) __nv_bfloat16 g_hA_hi[Bz * Hz], g_hA_lo[Bz * Hz];
__device__ __align__(1024) __nv_bfloat16 g_hB_hi[Bz * Hz], g_hB_lo[Bz * Hz];
__device__ __align__(1024) __nv_bfloat16 g_r_hi[Bz * Hz],  g_r_lo[Bz * Hz];
__device__ __align__(1024) __nv_bfloat16 g_msg_hi[Lz * Bz * MVz], g_msg_lo[Lz * Bz * MVz];
__device__ __align__(1024) __nv_bfloat16 g_din_hi[(size_t)Tz * Bz * Hz], g_din_lo[(size_t)Tz * Bz * Hz];
__device__ __align__(1024) __nv_bfloat16 g_hist_hi[(size_t)Tz * Bz * Hz], g_hist_lo[(size_t)Tz * Bz * Hz];

__device__ __align__(1024) __nv_bfloat16 w_setWih_hi[H4z * Hz],  w_setWih_lo[H4z * Hz];
__device__ __align__(1024) __nv_bfloat16 w_genWhh_hi[H4z * Hz],  w_genWhh_lo[H4z * Hz];
__device__ __align__(1024) __nv_bfloat16 w_mencWih_hi[H4z * MVz], w_mencWih_lo[H4z * MVz];
__device__ __align__(1024) __nv_bfloat16 w_mencWhh_hi[H4z * Hz], w_mencWhh_lo[H4z * Hz];
__device__ __align__(1024) __nv_bfloat16 w_decWih_hi[H4z * Hz],  w_decWih_lo[H4z * Hz];
__device__ __align__(1024) __nv_bfloat16 w_decWhh_hi[H4z * Hz],  w_decWhh_lo[H4z * Hz];
__device__ __align__(1024) __nv_bfloat16 w_outW_hi[Vz * Hz],     w_outW_lo[Vz * Hz];

__device__ __forceinline__ float sigm(float x) { return 1.f / (1.f + expf(-x)); }
__device__ __forceinline__ void split_bf(float v, __nv_bfloat16& hi, __nv_bfloat16& lo) {
    __nv_bfloat16 h = __float2bfloat16(v);
    hi = h;
    lo = __float2bfloat16(v - __bfloat162float(h));
}

// ===================== small kernels ========================================
// plain blocked split (for output projection weight)
__global__ void split_w_blk_kernel(const float* __restrict__ x, __nv_bfloat16* __restrict__ hi,
                                   __nv_bfloat16* __restrict__ lo, int K, int n) {
    int i = blockIdx.x * blockDim.x + threadIdx.x;
    if (i >= n) return;
    size_t bi = blk_idx(i / K, i % K, K);
    split_bf(x[i], hi[bi], lo[bi]);
}

// gate-interleaved blocked split: original row j (gate g=j/H, unit u=j%H) -> 4u+g
__global__ void split_w_blk_gate_kernel(const float* __restrict__ x, __nv_bfloat16* __restrict__ hi,
                                        __nv_bfloat16* __restrict__ lo, int K, int n) {
    int i = blockIdx.x * blockDim.x + threadIdx.x;
    if (i >= n) return;
    int j = i / K, k = i % K;
    int jp = 4 * (j & (Hz - 1)) + (j >> 10);
    size_t bi = blk_idx(jp, k, K);
    split_bf(x[i], hi[bi], lo[bi]);
}

// interleaved combined gate bias: out[4u+g] = bih[j]+bhh[j]+extra[j]
__global__ void bias4_kernel(const float* __restrict__ bih, const float* __restrict__ bhh,
                             const float* __restrict__ extra, float* __restrict__ out) {
    int j = blockIdx.x * blockDim.x + threadIdx.x;
    if (j >= H4z) return;
    float v = bih[j] + bhh[j] + (extra ? extra[j] : 0.f);
    out[4 * (j & (Hz - 1)) + (j >> 10)] = v;
}

__global__ void vecmat_kernel(const float* __restrict__ x, const float* __restrict__ Wt,
                              float* __restrict__ y, int N, int K) {
    int j = blockIdx.x * (blockDim.x / 32) + (threadIdx.x >> 5);
    int lane = threadIdx.x & 31;
    if (j >= N) return;
    const float* w = Wt + (size_t)j * K;
    float s = 0.f;
    for (int k = lane; k < K; k += 32) s += x[k] * w[k];
    #pragma unroll
    for (int o = 16; o; o >>= 1) s += __shfl_xor_sync(0xffffffffu, s, o);
    if (lane == 0) y[j] = s;
}

__global__ void attn_aw_kernel(const int* __restrict__ ivar, const float* __restrict__ mask,
                               const float* __restrict__ emb, const float* __restrict__ attw,
                               const float* __restrict__ attb) {
    int p = blockIdx.x * (blockDim.x / 32) + (threadIdx.x >> 5);
    if (p >= Bz * Wz) return;
    int lane = threadIdx.x & 31;
    int b = p / Wz, w = p % Wz;
    const float* e  = emb + (size_t)ivar[p] * Hz;
    const float* wv = attw + Hz;
    float s = 0.f;
    for (int k = lane; k < Hz; k += 32) s += e[k] * wv[k];
    #pragma unroll
    for (int o = 16; o; o >>= 1) s += __shfl_xor_sync(0xffffffffu, s, o);
    if (lane == 0) {
        float v = sigm(s + g_s0 + attb[0]);
        g_aw[p] = v * mask[w * Bz + b];
    }
}

__global__ void attn_r_kernel(const int* __restrict__ ivar, const float* __restrict__ emb) {
    int b  = blockIdx.x;
    int h0 = threadIdx.x * 4;
    float a[4] = {0.f, 0.f, 0.f, 0.f};
    for (int w = 0; w < Wz; ++w) {
        float aw = g_aw[b * Wz + w];
        float4 e = *(const float4*)(emb + (size_t)ivar[b * Wz + w] * Hz + h0);
        a[0] += aw * e.x; a[1] += aw * e.y; a[2] += aw * e.z; a[3] += aw * e.w;
    }
    #pragma unroll
    for (int j = 0; j < 4; ++j) {
        size_t bi = blk_idx(b, h0 + j, Hz);
        split_bf(a[j], g_r_hi[bi], g_r_lo[bi]);
    }
}

// broadcast (1,H) row into g_h (+ splits into given buffers) or g_c
__global__ void bcast_BH_kernel(const float* __restrict__ src, int which,
                                __nv_bfloat16* __restrict__ hh, __nv_bfloat16* __restrict__ hl) {
    int i = blockIdx.x * blockDim.x + threadIdx.x;
    if (i >= Bz * Hz) return;
    int b = i / Hz, hi = i % Hz;
    float v = src[hi];
    if (which == 0) {
        g_h[i] = v;
        size_t bi = blk_idx(b, hi, Hz);
        split_bf(v, hh[bi], hl[bi]);
    } else g_c[i] = v;
}

__global__ void init_m_kernel() {
    int i = blockIdx.x * blockDim.x + threadIdx.x;
    if (i < Bz) g_m[i] = 1.f;
}

__global__ void dec_gather_kernel(const int* __restrict__ tvar, const float* __restrict__ emb) {
    size_t i = (size_t)blockIdx.x * blockDim.x + threadIdx.x;
    if (i >= (size_t)Tz * Bz * Hz) return;
    int hi = (int)(i % Hz);
    size_t bt = i / Hz;
    int b = (int)(bt % Bz);
    int t = (int)(bt / Bz);
    int row = (t == 0) ? SOSI : tvar[(t - 1) * Bz + b];
    size_t bi = (size_t)t * (Bz * Hz) + blk_idx(b, hi, Hz);
    split_bf(emb[(size_t)row * Hz + hi], g_din_hi[bi], g_din_lo[bi]);
}

__global__ void gen_out_kernel(const float* __restrict__ outW, const float* __restrict__ outb,
                               int t) {
    int b = blockIdx.x;
    int tid = threadIdx.x;
    int warp = tid >> 5, lane = tid & 31;
    __shared__ float logits[MVz];
    __shared__ float red[2];
    const float* hrow = g_h + (size_t)b * Hz;
    for (int j = warp; j < MVz; j += 8) {
        const float* wrow = outW + (size_t)j * Hz;
        float s = 0.f;
        for (int k = lane; k < Hz; k += 32) s += hrow[k] * wrow[k];
        #pragma unroll
        for (int o = 16; o; o >>= 1) s += __shfl_xor_sync(0xffffffffu, s, o);
        if (lane == 0) logits[j] = s + outb[j];
    }
    __syncthreads();
    if (tid < 32) {
        float v1 = logits[tid], v2 = logits[tid + 32];
        float mx = fmaxf(v1, v2);
        #pragma unroll
        for (int o = 16; o; o >>= 1) mx = fmaxf(mx, __shfl_xor_sync(0xffffffffu, mx, o));
        float s = expf(v1 - mx) + expf(v2 - mx);
        #pragma unroll
        for (int o = 16; o; o >>= 1) s += __shfl_xor_sync(0xffffffffu, s, o);
        if (tid == 0) { red[0] = mx; red[1] = s; }
    }
    __syncthreads();
    if (tid < MVz) {
        float p = expf(logits[tid] - red[0]) / red[1];
        size_t bi = (size_t)t * (Bz * MVz) + blk_idx(b, tid, MVz);
        split_bf(p, g_msg_hi[bi], g_msg_lo[bi]);
        if (tid == EOSI) {
            g_mmask[t * Bz + b] = g_m[b];
            g_m[b] = g_m[b] * (1.f - p);
        }
    }
}

// ===================== bulk-copy mma.sync GEMM + fused epilogue =============
// C = A1@W1^T + A2@W2^T; operands blocked bf16 hi/lo, 3-phase split reuse.
// mode 0: C store + bias.  mode 1: LSTM gate epilogue (gate-interleaved N):
//   128-col tile = 32 complete hidden units; computes cell update, writes
//   g_h/g_c, bf16 h splits (double-buffered) or history slice.

#define STG 65536
#define TC_SMEM_BYTES (1024 + 3 * STG)

__device__ __forceinline__ void issue_stage(
    int s, int buf, uint32_t sb, int mt, int nt,
    const __nv_bfloat16* Ah1, const __nv_bfloat16* Al1,
    const __nv_bfloat16* Wh1, const __nv_bfloat16* Wl1, int C1,
    const __nv_bfloat16* Ah2, const __nv_bfloat16* Al2,
    const __nv_bfloat16* Wh2, const __nv_bfloat16* Wl2, int C2)
{
    const __nv_bfloat16 *Ah, *Al, *Wh, *Wl; size_t ao, wo;
    if (s < C1) {
        Ah = Ah1; Al = Al1; Wh = Wh1; Wl = Wl1;
        ao = ((size_t)(mt * C1 + s)) << 13;
        wo = ((size_t)(nt * C1 + s)) << 13;
    } else {
        const int c = s - C1;
        Ah = Ah2; Al = Al2; Wh = Wh2; Wl = Wl2;
        ao = ((size_t)(mt * C2 + c)) << 13;
        wo = ((size_t)(nt * C2 + c)) << 13;
    }
    const uint32_t d = sb + 1024 + buf * STG;
    const uint32_t m = sb + buf * 8;
    asm volatile("mbarrier.arrive.expect_tx.shared.b64 _, [%0], %1;"
                 :: "r"(m), "r"(65536u) : "memory");
    bulkcp(d,         Ah + ao, m);
    bulkcp(d + 16384, Al + ao, m);
    bulkcp(d + 32768, Wh + wo, m);
    bulkcp(d + 49152, Wl + wo, m);
}

__global__ __launch_bounds__(256) void tc_gemm(
    const __nv_bfloat16* __restrict__ Ah1, const __nv_bfloat16* __restrict__ Al1,
    const __nv_bfloat16* __restrict__ Wh1, const __nv_bfloat16* __restrict__ Wl1, int K1,
    const __nv_bfloat16* __restrict__ Ah2, const __nv_bfloat16* __restrict__ Al2,
    const __nv_bfloat16* __restrict__ Wh2, const __nv_bfloat16* __restrict__ Wl2, int K2,
    const float* __restrict__ bias, float* __restrict__ C, int Ntot, int mode,
    float* __restrict__ hptr, float* __restrict__ cptr, const float* __restrict__ maskp,
    __nv_bfloat16* __restrict__ ohh, __nv_bfloat16* __restrict__ ohl,
    __nv_bfloat16* __restrict__ histh, __nv_bfloat16* __restrict__ histl, int histbase)
{
    extern __shared__ char smem[];
    const uint32_t sb = smem_u32(smem);
    const int tid = threadIdx.x;
    const int wid = tid >> 5, lane = tid & 31;
    const int wm = wid & 1, wn = wid >> 1;
    const int mt = blockIdx.y, nt = blockIdx.x;
    const int m0 = mt * 128, n0 = nt * 128;
    const int C1 = K1 >> 6, C2 = K2 >> 6;
    const int S = C1 + C2;

    if (tid == 0) {
        MBARRIER_INIT(sb, 1);
        MBARRIER_INIT(sb + 8, 1);
        MBARRIER_INIT(sb + 16, 1);
    }
    __syncthreads();
    if (tid == 0) {
        issue_stage(0, 0, sb, mt, nt, Ah1, Al1, Wh1, Wl1, C1, Ah2, Al2, Wh2, Wl2, C2);
        if (S > 1) issue_stage(1, 1, sb, mt, nt, Ah1, Al1, Wh1, Wl1, C1, Ah2, Al2, Wh2, Wl2, C2);
        if (S > 2) issue_stage(2, 2, sb, mt, nt, Ah1, Al1, Wh1, Wl1, C1, Ah2, Al2, Wh2, Wl2, C2);
    }

    float acc[4][4][4];
    #pragma unroll
    for (int i = 0; i < 4; ++i)
        #pragma unroll
        for (int j = 0; j < 4; ++j)
            #pragma unroll
            for (int k = 0; k < 4; ++k) acc[i][j][k] = 0.f;

    const int tsel = lane >> 3;
    const int trow = lane & 7;
    int ph[3] = {0, 0, 0};

    for (int s = 0; s < S; ++s) {
        const int buf = s % 3;
        MBAR_WAIT(sb + buf * 8, ph[buf]);
        ph[buf] ^= 1;
        const uint32_t Ab  = sb + 1024 + buf * STG;
        const uint32_t Alb = Ab + 16384;
        const uint32_t Wb  = Ab + 32768;
        const uint32_t Wlb = Ab + 49152;

        #pragma unroll
        for (int ks = 0; ks < 4; ++ks) {
            uint32_t ah[4][4], al[4][4], bh[2][4], bl[2][4];
            #pragma unroll
            for (int mi = 0; mi < 4; ++mi) {
                const int row = wm * 64 + mi * 16 + (tsel & 1) * 8 + trow;
                const uint32_t off = row * 128 +
                    (uint32_t)((((ks * 2 + (tsel >> 1)) ^ (row & 7)) << 4));
                ldsm_x4(ah[mi], Ab + off);
                ldsm_x4(al[mi], Alb + off);
            }
            #pragma unroll
            for (int np = 0; np < 2; ++np) {
                const int n = wn * 32 + np * 16 + (tsel >> 1) * 8 + trow;
                const uint32_t off = n * 128 +
                    (uint32_t)((((ks * 2 + (tsel & 1)) ^ (n & 7)) << 4));
                ldsm_x4(bh[np], Wb + off);
                ldsm_x4(bl[np], Wlb + off);
            }
            #pragma unroll
            for (int mi = 0; mi < 4; ++mi)
                #pragma unroll
                for (int ni = 0; ni < 4; ++ni) {
                    const uint32_t h0 = bh[ni >> 1][(ni & 1) * 2];
                    const uint32_t h1 = bh[ni >> 1][(ni & 1) * 2 + 1];
                    const uint32_t l0 = bl[ni >> 1][(ni & 1) * 2];
                    const uint32_t l1 = bl[ni >> 1][(ni & 1) * 2 + 1];
                    mma_bf16(acc[mi][ni], ah[mi], h0, h1);
                    mma_bf16(acc[mi][ni], al[mi], h0, h1);
                    mma_bf16(acc[mi][ni], ah[mi], l0, l1);
                }
        }
        __syncthreads();
        if (tid == 0 && s + 3 < S)
            issue_stage(s + 3, buf, sb, mt, nt, Ah1, Al1, Wh1, Wl1, C1, Ah2, Al2, Wh2, Wl2, C2);
    }

    const int erow = lane >> 2;
    const int ecol = (lane & 3) * 2;

    if (mode == 0) {
        #pragma unroll
        for (int mi = 0; mi < 4; ++mi) {
            const int r0 = m0 + wm * 64 + mi * 16 + erow;
            #pragma unroll
            for (int ni = 0; ni < 4; ++ni) {
                const int n = n0 + wn * 32 + ni * 8 + ecol;
                float b0 = 0.f, b1 = 0.f;
                if (bias) { b0 = bias[n]; b1 = bias[n + 1]; }
                float2 v0 = make_float2(acc[mi][ni][0] + b0, acc[mi][ni][1] + b1);
                float2 v1 = make_float2(acc[mi][ni][2] + b0, acc[mi][ni][3] + b1);
                *(float2*)(C + (size_t)r0 * Ntot + n)       = v0;
                *(float2*)(C + (size_t)(r0 + 8) * Ntot + n) = v1;
            }
        }
        return;
    }

    // ---- mode 1: fused LSTM gate epilogue ----
    float* sT = (float*)(smem + 1024);
    #pragma unroll
    for (int mi = 0; mi < 4; ++mi) {
        const int rl = wm * 64 + mi * 16 + erow;
        #pragma unroll
        for (int ni = 0; ni < 4; ++ni) {
            const int nl = wn * 32 + ni * 8 + ecol;
            const float b0 = bias[n0 + nl], b1 = bias[n0 + nl + 1];
            *(float2*)(sT + rl * 132 + nl) =
                make_float2(acc[mi][ni][0] + b0, acc[mi][ni][1] + b1);
            *(float2*)(sT + (rl + 8) * 132 + nl) =
                make_float2(acc[mi][ni][2] + b0, acc[mi][ni][3] + b1);
        }
    }
    __syncthreads();

    const int ubase = n0 >> 2;
    for (int cix = tid; cix < 4096; cix += 256) {
        const int r = cix >> 5, uu = cix & 31;
        const float4 gv = *(const float4*)(sT + r * 132 + uu * 4);
        const int b = m0 + r, u = ubase + uu;
        const int gi = b * Hz + u;
        const float cp = cptr[gi];
        float cn = sigm(gv.y) * cp + sigm(gv.x) * tanhf(gv.z);
        float hn = sigm(gv.w) * tanhf(cn);
        if (maskp) {
            const float mv = maskp[b];
            hn = mv * hn + (1.f - mv) * hptr[gi];
            cn = mv * cn + (1.f - mv) * cp;
        }
        cptr[gi] = cn;
        __nv_bfloat16 vh, vl;
        split_bf(hn, vh, vl);
        if (histh) {
            const size_t bi = blk_idx(histbase + b, u, Hz);
            histh[bi] = vh; histl[bi] = vl;
        } else {
            hptr[gi] = hn;
            const size_t bi = blk_idx(b, u, Hz);
            ohh[bi] = vh; ohl[bi] = vl;
        }
    }
}

// ===================== host driver ==========================================
extern "C" void kernel_launch(void* const* d_in, const int* in_sizes, int n_in,
                              void* d_out, int out_size) {
    int s = (in_sizes[3] <= 16) ? 0 : -1;

    const int*   input_var  = (const int*)  d_in[0];
    const float* input_mask = (const float*)d_in[1];
    const int*   target_var = (const int*)  d_in[2];
    const float* emb      = (const float*)d_in[4 + s];
    const float* attn_w   = (const float*)d_in[5 + s];
    const float* attn_b   = (const float*)d_in[6 + s];
    const float* set_Wih  = (const float*)d_in[7 + s];
    const float* set_Whh  = (const float*)d_in[8 + s];
    const float* set_bih  = (const float*)d_in[9 + s];
    const float* set_bhh  = (const float*)d_in[10 + s];
    const float* set_h0   = (const float*)d_in[11 + s];
    const float* set_c0   = (const float*)d_in[12 + s];
    const float* gen_x0   = (const float*)d_in[13 + s];
    const float* gen_Wih  = (const float*)d_in[14 + s];
    const float* gen_Whh  = (const float*)d_in[15 + s];
    const float* gen_bih  = (const float*)d_in[16 + s];
    const float* gen_bhh  = (const float*)d_in[17 + s];
    const float* gen_outW = (const float*)d_in[18 + s];
    const float* gen_outb = (const float*)d_in[19 + s];
    const float* menc_Wih = (const float*)d_in[20 + s];
    const float* menc_Whh = (const float*)d_in[21 + s];
    const float* menc_bih = (const float*)d_in[22 + s];
    const float* menc_bhh = (const float*)d_in[23 + s];
    const float* menc_h0  = (const float*)d_in[24 + s];
    const float* menc_c0  = (const float*)d_in[25 + s];
    const float* dec_Wih  = (const float*)d_in[26 + s];
    const float* dec_Whh  = (const float*)d_in[27 + s];
    const float* dec_bih  = (const float*)d_in[28 + s];
    const float* dec_bhh  = (const float*)d_in[29 + s];
    const float* dec_outW = (const float*)d_in[30 + s];
    const float* dec_outb = (const float*)d_in[31 + s];
    float* out = (float*)d_out;

    cudaFuncSetAttribute(tc_gemm, cudaFuncAttributeMaxDynamicSharedMemorySize, TC_SMEM_BYTES);

    float *p_h, *p_c, *p_hb, *p_xb, *p_s0, *p_mmask;
    float *gb_set, *gb_gen, *gb_menc, *gb_dec;
    cudaGetSymbolAddress((void**)&p_h,     g_h);
    cudaGetSymbolAddress((void**)&p_c,     g_c);
    cudaGetSymbolAddress((void**)&p_hb,    g_hb_enc);
    cudaGetSymbolAddress((void**)&p_xb,    g_xb_gen);
    cudaGetSymbolAddress((void**)&p_s0,    g_s0);
    cudaGetSymbolAddress((void**)&p_mmask, g_mmask);
    cudaGetSymbolAddress((void**)&gb_set,  g_gb_set);
    cudaGetSymbolAddress((void**)&gb_gen,  g_gb_gen);
    cudaGetSymbolAddress((void**)&gb_menc, g_gb_menc);
    cudaGetSymbolAddress((void**)&gb_dec,  g_gb_dec);

    __nv_bfloat16 *hAh, *hAl, *hBh, *hBl, *rh, *rl, *mh, *ml, *dh, *dl, *hsh, *hsl;
    cudaGetSymbolAddress((void**)&hAh, g_hA_hi); cudaGetSymbolAddress((void**)&hAl, g_hA_lo);
    cudaGetSymbolAddress((void**)&hBh, g_hB_hi); cudaGetSymbolAddress((void**)&hBl, g_hB_lo);
    cudaGetSymbolAddress((void**)&rh, g_r_hi);   cudaGetSymbolAddress((void**)&rl, g_r_lo);
    cudaGetSymbolAddress((void**)&mh, g_msg_hi); cudaGetSymbolAddress((void**)&ml, g_msg_lo);
    cudaGetSymbolAddress((void**)&dh, g_din_hi); cudaGetSymbolAddress((void**)&dl, g_din_lo);
    cudaGetSymbolAddress((void**)&hsh, g_hist_hi); cudaGetSymbolAddress((void**)&hsl, g_hist_lo);

    __nv_bfloat16 *sWih_h, *sWih_l, *gWhh_h, *gWhh_l, *mWih_h, *mWih_l,
                  *mWhh_h, *mWhh_l, *dWih_h, *dWih_l, *dWhh_h, *dWhh_l, *oW_h, *oW_l;
    cudaGetSymbolAddress((void**)&sWih_h, w_setWih_hi);  cudaGetSymbolAddress((void**)&sWih_l, w_setWih_lo);
    cudaGetSymbolAddress((void**)&gWhh_h, w_genWhh_hi);  cudaGetSymbolAddress((void**)&gWhh_l, w_genWhh_lo);
    cudaGetSymbolAddress((void**)&mWih_h, w_mencWih_hi); cudaGetSymbolAddress((void**)&mWih_l, w_mencWih_lo);
    cudaGetSymbolAddress((void**)&mWhh_h, w_mencWhh_hi); cudaGetSymbolAddress((void**)&mWhh_l, w_mencWhh_lo);
    cudaGetSymbolAddress((void**)&dWih_h, w_decWih_hi);  cudaGetSymbolAddress((void**)&dWih_l, w_decWih_lo);
    cudaGetSymbolAddress((void**)&dWhh_h, w_decWhh_hi);  cudaGetSymbolAddress((void**)&dWhh_l, w_decWhh_lo);
    cudaGetSymbolAddress((void**)&oW_h,   w_outW_hi);    cudaGetSymbolAddress((void**)&oW_l,   w_outW_lo);

    const dim3 gBig(H4z / 128, Bz / 128);     // (32, 4) gate GEMMs
    const dim3 gFin(Vz / 128, (Tz * Bz) / 128); // (8, 200) final batched projection
    const int SPLIT_T = 256;
    const int BC_B = (Bz * Hz + 255) / 256;

    // ---- weight splits (gate-interleaved for recurrent mats) ----
    split_w_blk_gate_kernel<<<(H4z * Hz + SPLIT_T - 1) / SPLIT_T, SPLIT_T>>>(set_Wih,  sWih_h, sWih_l, Hz,  H4z * Hz);
    split_w_blk_gate_kernel<<<(H4z * Hz + SPLIT_T - 1) / SPLIT_T, SPLIT_T>>>(gen_Whh,  gWhh_h, gWhh_l, Hz,  H4z * Hz);
    split_w_blk_gate_kernel<<<(H4z * MVz + SPLIT_T - 1) / SPLIT_T, SPLIT_T>>>(menc_Wih, mWih_h, mWih_l, MVz, H4z * MVz);
    split_w_blk_gate_kernel<<<(H4z * Hz + SPLIT_T - 1) / SPLIT_T, SPLIT_T>>>(menc_Whh, mWhh_h, mWhh_l, Hz,  H4z * Hz);
    split_w_blk_gate_kernel<<<(H4z * Hz + SPLIT_T - 1) / SPLIT_T, SPLIT_T>>>(dec_Wih,  dWih_h, dWih_l, Hz,  H4z * Hz);
    split_w_blk_gate_kernel<<<(H4z * Hz + SPLIT_T - 1) / SPLIT_T, SPLIT_T>>>(dec_Whh,  dWhh_h, dWhh_l, Hz,  H4z * Hz);
    split_w_blk_kernel<<<(Vz * Hz + SPLIT_T - 1) / SPLIT_T, SPLIT_T>>>(dec_outW, oW_h, oW_l, Hz, Vz * Hz);

    // ---- precompute ----
    vecmat_kernel<<<1, 32>>>(set_h0, attn_w, p_s0, 1, Hz);
    vecmat_kernel<<<H4z / 8, 256>>>(set_h0, set_Whh, p_hb, H4z, Hz);
    vecmat_kernel<<<H4z / 8, 256>>>(gen_x0, gen_Wih, p_xb, H4z, MVz);
    bias4_kernel<<<H4z / 256, 256>>>(set_bih,  set_bhh,  p_hb,    gb_set);
    bias4_kernel<<<H4z / 256, 256>>>(gen_bih,  gen_bhh,  p_xb,    gb_gen);
    bias4_kernel<<<H4z / 256, 256>>>(menc_bih, menc_bhh, nullptr, gb_menc);
    bias4_kernel<<<H4z / 256, 256>>>(dec_bih,  dec_bhh,  nullptr, gb_dec);
    attn_aw_kernel<<<(Bz * Wz + 7) / 8, 256>>>(input_var, input_mask, emb, attn_w, attn_b);
    attn_r_kernel<<<Bz, 256>>>(input_var, emb);
    dec_gather_kernel<<<(int)(((size_t)Tz * Bz * Hz + 255) / 256), 256>>>(target_var, emb);
    init_m_kernel<<<2, 256>>>();

    // double-buffered h splits (read cur, gate writes nxt)
    __nv_bfloat16 *curh = hAh, *curl = hAl, *nxth = hBh, *nxtl = hBl;

    // ---- set encoder (A1 = r; h0 contribution folded into gb_set) ----
    bcast_BH_kernel<<<BC_B, 256>>>(set_c0, 1, nullptr, nullptr);
    tc_gemm<<<gBig, 256, TC_SMEM_BYTES>>>(rh, rl, sWih_h, sWih_l, Hz,
                                          nullptr, nullptr, nullptr, nullptr, 0,
                                          gb_set, nullptr, H4z, 1,
                                          p_h, p_c, nullptr, nxth, nxtl, nullptr, nullptr, 0);
    { auto th = curh; curh = nxth; nxth = th; auto tl = curl; curl = nxtl; nxtl = tl; }

    // ---- generator loop ----
    for (int t = 0; t < Lz; ++t) {
        tc_gemm<<<gBig, 256, TC_SMEM_BYTES>>>(curh, curl, gWhh_h, gWhh_l, Hz,
                                              nullptr, nullptr, nullptr, nullptr, 0,
                                              gb_gen, nullptr, H4z, 1,
                                              p_h, p_c, nullptr, nxth, nxtl, nullptr, nullptr, 0);
        { auto th = curh; curh = nxth; nxth = th; auto tl = curl; curl = nxtl; nxtl = tl; }
        gen_out_kernel<<<Bz, 256>>>(gen_outW, gen_outb, t);
    }

    // ---- message encoder loop ----
    bcast_BH_kernel<<<BC_B, 256>>>(menc_h0, 0, curh, curl);
    bcast_BH_kernel<<<BC_B, 256>>>(menc_c0, 1, nullptr, nullptr);
    for (int t = 0; t < Lz; ++t) {
        tc_gemm<<<gBig, 256, TC_SMEM_BYTES>>>(mh + (size_t)t * Bz * MVz, ml + (size_t)t * Bz * MVz,
                                              mWih_h, mWih_l, MVz,
                                              curh, curl, mWhh_h, mWhh_l, Hz,
                                              gb_menc, nullptr, H4z, 1,
                                              p_h, p_c, p_mmask + (size_t)t * Bz,
                                              nxth, nxtl, nullptr, nullptr, 0);
        { auto th = curh; curh = nxth; nxth = th; auto tl = curl; curl = nxtl; nxtl = tl; }
    }

    // ---- decoder loop (gate writes history slice; out-proj deferred) ----
    for (int t = 0; t < Tz; ++t) {
        const __nv_bfloat16* a2h = (t == 0) ? curh : hsh + (size_t)(t - 1) * Bz * Hz;
        const __nv_bfloat16* a2l = (t == 0) ? curl : hsl + (size_t)(t - 1) * Bz * Hz;
        tc_gemm<<<gBig, 256, TC_SMEM_BYTES>>>(dh + (size_t)t * Bz * Hz, dl + (size_t)t * Bz * Hz,
                                              dWih_h, dWih_l, Hz,
                                              a2h, a2l, dWhh_h, dWhh_l, Hz,
                                              gb_dec, nullptr, H4z, 1,
                                              p_h, p_c, nullptr, nullptr, nullptr,
                                              hsh, hsl, t * Bz);
    }

    // ---- deferred batched output projection: logits[t,b,:] ----
    tc_gemm<<<gFin, 256, TC_SMEM_BYTES>>>(hsh, hsl, oW_h, oW_l, Hz,
                                          nullptr, nullptr, nullptr, nullptr, 0,
                                          dec_outb, out, Vz, 0,
                                          nullptr, nullptr, nullptr, nullptr, nullptr,
                                          nullptr, nullptr, 0);
    (void)n_in; (void)out_size;
}

// round 11
// speedup vs baseline: 1.5927x; 1.5927x over previous
#include <cuda_runtime.h>
#include <cuda_bf16.h>
#include <cstdint>
#include <cstdio>

#define Bz   512
#define Wz   50
#define Tz   50
#define Hz   1024
#define Vz   1024
#define MVz  64
#define Lz   30
#define H4z  4096
#define SOSI 0
#define EOSI 1

// ===================== PTX helpers (base sm_103 ISA only) ===================
__device__ __forceinline__ uint32_t smem_u32(const void* p) {
    uint32_t a;
    asm("{ .reg .u64 t; cvta.to.shared.u64 t, %1; cvt.u32.u64 %0, t; }" : "=r"(a) : "l"(p));
    return a;
}
#define MBARRIER_INIT(addr, cnt) \
    asm volatile("mbarrier.init.shared.b64 [%0], %1;" :: "r"((uint32_t)(addr)), "r"((uint32_t)(cnt)) : "memory")
#define MBAR_WAIT(addr, parity) do {                                              \
    uint32_t _mb = (uint32_t)(addr); uint32_t _pp = (uint32_t)(parity);           \
    uint32_t _done;                                                               \
    asm volatile("{\n\t.reg .pred p;\n\t"                                         \
        "mbarrier.try_wait.parity.acquire.cta.shared::cta.b64 p, [%1], %2;\n\t"   \
        "selp.b32 %0, 1, 0, p;\n\t}" : "=r"(_done) : "r"(_mb), "r"(_pp) : "memory"); \
    if (!_done) {                                                                 \
        asm volatile("{\n\t.reg .pred P1;\n\t"                                    \
            "WL_%=:\n\t"                                                          \
            "mbarrier.try_wait.parity.acquire.cta.shared::cta.b64 P1, [%0], %1, 0x989680;\n\t" \
            "@P1 bra.uni WD_%=;\n\t"                                              \
            "bra.uni WL_%=;\n\t"                                                  \
            "WD_%=:\n\t}" :: "r"(_mb), "r"(_pp) : "memory");                      \
    }                                                                             \
} while (0)

__device__ __forceinline__ void bulkcp(uint32_t dst, const void* src, uint32_t mbar) {
    asm volatile("cp.async.bulk.shared::cluster.global.mbarrier::complete_tx::bytes [%0], [%1], %2, [%3];"
        :: "r"(dst), "l"(src), "r"(16384u), "r"(mbar) : "memory");
}
__device__ __forceinline__ void ldsm_x4(uint32_t* r, uint32_t addr) {
    asm volatile("ldmatrix.sync.aligned.m8n8.x4.shared.b16 {%0,%1,%2,%3}, [%4];"
                 : "=r"(r[0]), "=r"(r[1]), "=r"(r[2]), "=r"(r[3]) : "r"(addr));
}
__device__ __forceinline__ void mma_bf16(float* c, const uint32_t* a, uint32_t b0, uint32_t b1) {
    asm volatile("mma.sync.aligned.m16n8k16.row.col.f32.bf16.bf16.f32 "
                 "{%0,%1,%2,%3}, {%4,%5,%6,%7}, {%8,%9}, {%0,%1,%2,%3};"
                 : "+f"(c[0]), "+f"(c[1]), "+f"(c[2]), "+f"(c[3])
                 : "r"(a[0]), "r"(a[1]), "r"(a[2]), "r"(a[3]), "r"(b0), "r"(b1));
}

// ===================== blocked (tile-image) layout ==========================
__device__ __forceinline__ size_t blk_idx(int r, int k, int K) {
    const int rt = r >> 7, kc = k >> 6;
    const int rr = r & 127, kk = k & 63;
    const int gs = (kk >> 3) ^ (rr & 7);
    return ((size_t)(rt * (K >> 6) + kc) << 13) + rr * 64 + gs * 8 + (kk & 7);
}

// ===================== scratch (device globals) =============================
__device__ float g_g[Bz * H4z];
__device__ float g_h[Bz * Hz];
__device__ float g_c[Bz * Hz];
__device__ float g_aw[Bz * Wz];
__device__ float g_mmask[Lz * Bz];
__device__ float g_m[Bz];
__device__ float g_hb_enc[H4z];
__device__ float g_xb_gen[H4z];
__device__ float g_s0;
__device__ float g_gb_set[H4z], g_gb_gen[H4z], g_gb_menc[H4z], g_gb_dec[H4z];

__device__ __align__(1024) __nv_bfloat16 g_h_hi[Bz * Hz],  g_h_lo[Bz * Hz];
__device__ __align__(1024) __nv_bfloat16 g_r_hi[Bz * Hz],  g_r_lo[Bz * Hz];
__device__ __align__(1024) __nv_bfloat16 g_msg_hi[Lz * Bz * MVz], g_msg_lo[Lz * Bz * MVz];
__device__ __align__(1024) __nv_bfloat16 g_din_hi[(size_t)Tz * Bz * Hz], g_din_lo[(size_t)Tz * Bz * Hz];
__device__ __align__(1024) __nv_bfloat16 g_hist_hi[(size_t)Tz * Bz * Hz], g_hist_lo[(size_t)Tz * Bz * Hz];

__device__ __align__(1024) __nv_bfloat16 w_setWih_hi[H4z * Hz],  w_setWih_lo[H4z * Hz];
__device__ __align__(1024) __nv_bfloat16 w_genWhh_hi[H4z * Hz],  w_genWhh_lo[H4z * Hz];
__device__ __align__(1024) __nv_bfloat16 w_mencWih_hi[H4z * MVz], w_mencWih_lo[H4z * MVz];
__device__ __align__(1024) __nv_bfloat16 w_mencWhh_hi[H4z * Hz], w_mencWhh_lo[H4z * Hz];
__device__ __align__(1024) __nv_bfloat16 w_decWih_hi[H4z * Hz],  w_decWih_lo[H4z * Hz];
__device__ __align__(1024) __nv_bfloat16 w_decWhh_hi[H4z * Hz],  w_decWhh_lo[H4z * Hz];
__device__ __align__(1024) __nv_bfloat16 w_outW_hi[Vz * Hz],     w_outW_lo[Vz * Hz];

__device__ __forceinline__ float sigm(float x) { return 1.f / (1.f + expf(-x)); }
__device__ __forceinline__ void split_bf(float v, __nv_bfloat16& hi, __nv_bfloat16& lo) {
    __nv_bfloat16 h = __float2bfloat16(v);
    hi = h;
    lo = __float2bfloat16(v - __bfloat162float(h));
}

// ===================== small kernels ========================================
__global__ void split_w_blk_kernel(const float* __restrict__ x, __nv_bfloat16* __restrict__ hi,
                                   __nv_bfloat16* __restrict__ lo, int K, int n) {
    int i = blockIdx.x * blockDim.x + threadIdx.x;
    if (i >= n) return;
    size_t bi = blk_idx(i / K, i % K, K);
    split_bf(x[i], hi[bi], lo[bi]);
}

// gate-interleaved: original row j (gate g=j/H, unit u=j%H) -> row 4u+g
__global__ void split_w_blk_gate_kernel(const float* __restrict__ x, __nv_bfloat16* __restrict__ hi,
                                        __nv_bfloat16* __restrict__ lo, int K, int n) {
    int i = blockIdx.x * blockDim.x + threadIdx.x;
    if (i >= n) return;
    int j = i / K, k = i % K;
    int jp = 4 * (j & (Hz - 1)) + (j >> 10);
    size_t bi = blk_idx(jp, k, K);
    split_bf(x[i], hi[bi], lo[bi]);
}

__global__ void bias4_kernel(const float* __restrict__ bih, const float* __restrict__ bhh,
                             const float* __restrict__ extra, float* __restrict__ out) {
    int j = blockIdx.x * blockDim.x + threadIdx.x;
    if (j >= H4z) return;
    float v = bih[j] + bhh[j] + (extra ? extra[j] : 0.f);
    out[4 * (j & (Hz - 1)) + (j >> 10)] = v;
}

__global__ void vecmat_kernel(const float* __restrict__ x, const float* __restrict__ Wt,
                              float* __restrict__ y, int N, int K) {
    int j = blockIdx.x * (blockDim.x / 32) + (threadIdx.x >> 5);
    int lane = threadIdx.x & 31;
    if (j >= N) return;
    const float* w = Wt + (size_t)j * K;
    float s = 0.f;
    for (int k = lane; k < K; k += 32) s += x[k] * w[k];
    #pragma unroll
    for (int o = 16; o; o >>= 1) s += __shfl_xor_sync(0xffffffffu, s, o);
    if (lane == 0) y[j] = s;
}

__global__ void attn_aw_kernel(const int* __restrict__ ivar, const float* __restrict__ mask,
                               const float* __restrict__ emb, const float* __restrict__ attw,
                               const float* __restrict__ attb) {
    int p = blockIdx.x * (blockDim.x / 32) + (threadIdx.x >> 5);
    if (p >= Bz * Wz) return;
    int lane = threadIdx.x & 31;
    int b = p / Wz, w = p % Wz;
    const float* e  = emb + (size_t)ivar[p] * Hz;
    const float* wv = attw + Hz;
    float s = 0.f;
    for (int k = lane; k < Hz; k += 32) s += e[k] * wv[k];
    #pragma unroll
    for (int o = 16; o; o >>= 1) s += __shfl_xor_sync(0xffffffffu, s, o);
    if (lane == 0) {
        float v = sigm(s + g_s0 + attb[0]);
        g_aw[p] = v * mask[w * Bz + b];
    }
}

__global__ void attn_r_kernel(const int* __restrict__ ivar, const float* __restrict__ emb) {
    int b  = blockIdx.x;
    int h0 = threadIdx.x * 4;
    float a[4] = {0.f, 0.f, 0.f, 0.f};
    for (int w = 0; w < Wz; ++w) {
        float aw = g_aw[b * Wz + w];
        float4 e = *(const float4*)(emb + (size_t)ivar[b * Wz + w] * Hz + h0);
        a[0] += aw * e.x; a[1] += aw * e.y; a[2] += aw * e.z; a[3] += aw * e.w;
    }
    #pragma unroll
    for (int j = 0; j < 4; ++j) {
        size_t bi = blk_idx(b, h0 + j, Hz);
        split_bf(a[j], g_r_hi[bi], g_r_lo[bi]);
    }
}

__global__ void bcast_BH_kernel(const float* __restrict__ src, int which) {
    int i = blockIdx.x * blockDim.x + threadIdx.x;
    if (i >= Bz * Hz) return;
    int b = i / Hz, hi = i % Hz;
    float v = src[hi];
    if (which == 0) {
        g_h[i] = v;
        size_t bi = blk_idx(b, hi, Hz);
        split_bf(v, g_h_hi[bi], g_h_lo[bi]);
    } else g_c[i] = v;
}

__global__ void init_m_kernel() {
    int i = blockIdx.x * blockDim.x + threadIdx.x;
    if (i < Bz) g_m[i] = 1.f;
}

__global__ void dec_gather_kernel(const int* __restrict__ tvar, const float* __restrict__ emb) {
    size_t i = (size_t)blockIdx.x * blockDim.x + threadIdx.x;
    if (i >= (size_t)Tz * Bz * Hz) return;
    int hi = (int)(i % Hz);
    size_t bt = i / Hz;
    int b = (int)(bt % Bz);
    int t = (int)(bt / Bz);
    int row = (t == 0) ? SOSI : tvar[(t - 1) * Bz + b];
    size_t bi = (size_t)t * (Bz * Hz) + blk_idx(b, hi, Hz);
    split_bf(emb[(size_t)row * Hz + hi], g_din_hi[bi], g_din_lo[bi]);
}

// gate kernel over interleaved g: g[b][4u+{i,f,g,o}], bias gb[4u+...] (float4)
// hist mode (histh != null): write blocked splits at row histbase+b.
__global__ void lstm_gate4_kernel(const float* __restrict__ gb, const float* __restrict__ maskp,
                                  __nv_bfloat16* __restrict__ histh, __nv_bfloat16* __restrict__ histl,
                                  int histbase) {
    int i = blockIdx.x * blockDim.x + threadIdx.x;
    if (i >= Bz * Hz) return;
    int b = i >> 10, u = i & (Hz - 1);
    float4 gv = *(const float4*)(g_g + ((size_t)b << 12) + 4 * u);
    float4 bb = *(const float4*)(gb + 4 * u);
    float cp = g_c[i];
    float cn = sigm(gv.y + bb.y) * cp + sigm(gv.x + bb.x) * tanhf(gv.z + bb.z);
    float hn = sigm(gv.w + bb.w) * tanhf(cn);
    if (maskp) {
        float mv = maskp[b];
        hn = mv * hn + (1.f - mv) * g_h[i];
        cn = mv * cn + (1.f - mv) * cp;
    }
    g_h[i] = hn;
    g_c[i] = cn;
    __nv_bfloat16 vh, vl;
    split_bf(hn, vh, vl);
    if (histh) {
        size_t bi = blk_idx(histbase + b, u, Hz);
        histh[bi] = vh; histl[bi] = vl;
    } else {
        size_t bi = blk_idx(b, u, Hz);
        g_h_hi[bi] = vh; g_h_lo[bi] = vl;
    }
}

// fused gen: gate (interleaved g) + softmax head + msg/mask, one block per b
__global__ __launch_bounds__(256) void gen_gate_out_kernel(
    const float* __restrict__ gb, const float* __restrict__ outW,
    const float* __restrict__ outb, int t) {
    __shared__ float hs[Hz];
    __shared__ float logits[MVz];
    __shared__ float red[2];
    const int b = blockIdx.x;
    const int tid = threadIdx.x;
    const int warp = tid >> 5, lane = tid & 31;

    #pragma unroll
    for (int it = 0; it < 4; ++it) {
        const int u = it * 256 + tid;
        const int i = (b << 10) + u;
        float4 gv = *(const float4*)(g_g + ((size_t)b << 12) + 4 * u);
        float4 bb = *(const float4*)(gb + 4 * u);
        float cp = g_c[i];
        float cn = sigm(gv.y + bb.y) * cp + sigm(gv.x + bb.x) * tanhf(gv.z + bb.z);
        float hn = sigm(gv.w + bb.w) * tanhf(cn);
        g_c[i] = cn;
        g_h[i] = hn;
        hs[u] = hn;
        __nv_bfloat16 vh, vl;
        split_bf(hn, vh, vl);
        size_t bi = blk_idx(b, u, Hz);
        g_h_hi[bi] = vh; g_h_lo[bi] = vl;
    }
    __syncthreads();

    for (int j = warp; j < MVz; j += 8) {
        const float* wrow = outW + (size_t)j * Hz;
        float s = 0.f;
        for (int k = lane; k < Hz; k += 32) s += hs[k] * wrow[k];
        #pragma unroll
        for (int o = 16; o; o >>= 1) s += __shfl_xor_sync(0xffffffffu, s, o);
        if (lane == 0) logits[j] = s + outb[j];
    }
    __syncthreads();
    if (tid < 32) {
        float v1 = logits[tid], v2 = logits[tid + 32];
        float mx = fmaxf(v1, v2);
        #pragma unroll
        for (int o = 16; o; o >>= 1) mx = fmaxf(mx, __shfl_xor_sync(0xffffffffu, mx, o));
        float s = expf(v1 - mx) + expf(v2 - mx);
        #pragma unroll
        for (int o = 16; o; o >>= 1) s += __shfl_xor_sync(0xffffffffu, s, o);
        if (tid == 0) { red[0] = mx; red[1] = s; }
    }
    __syncthreads();
    if (tid < MVz) {
        float p = expf(logits[tid] - red[0]) / red[1];
        size_t bi = (size_t)t * (Bz * MVz) + blk_idx(b, tid, MVz);
        split_bf(p, g_msg_hi[bi], g_msg_lo[bi]);
        if (tid == EOSI) {
            g_mmask[t * Bz + b] = g_m[b];
            g_m[b] = g_m[b] * (1.f - p);
        }
    }
}

// ===================== bulk-copy mma.sync GEMM (R5-proven) ==================
#define STG 65536
#define TC_SMEM_BYTES (1024 + 3 * STG)

__device__ __forceinline__ void issue_stage(
    int s, int buf, uint32_t sb, int mt, int nt,
    const __nv_bfloat16* Ah1, const __nv_bfloat16* Al1,
    const __nv_bfloat16* Wh1, const __nv_bfloat16* Wl1, int C1,
    const __nv_bfloat16* Ah2, const __nv_bfloat16* Al2,
    const __nv_bfloat16* Wh2, const __nv_bfloat16* Wl2, int C2)
{
    const __nv_bfloat16 *Ah, *Al, *Wh, *Wl; size_t ao, wo;
    if (s < C1) {
        Ah = Ah1; Al = Al1; Wh = Wh1; Wl = Wl1;
        ao = ((size_t)(mt * C1 + s)) << 13;
        wo = ((size_t)(nt * C1 + s)) << 13;
    } else {
        const int c = s - C1;
        Ah = Ah2; Al = Al2; Wh = Wh2; Wl = Wl2;
        ao = ((size_t)(mt * C2 + c)) << 13;
        wo = ((size_t)(nt * C2 + c)) << 13;
    }
    const uint32_t d = sb + 1024 + buf * STG;
    const uint32_t m = sb + buf * 8;
    asm volatile("mbarrier.arrive.expect_tx.shared.b64 _, [%0], %1;"
                 :: "r"(m), "r"(65536u) : "memory");
    bulkcp(d,         Ah + ao, m);
    bulkcp(d + 16384, Al + ao, m);
    bulkcp(d + 32768, Wh + wo, m);
    bulkcp(d + 49152, Wl + wo, m);
}

__global__ __launch_bounds__(256) void tc_gemm(
    const __nv_bfloat16* __restrict__ Ah1, const __nv_bfloat16* __restrict__ Al1,
    const __nv_bfloat16* __restrict__ Wh1, const __nv_bfloat16* __restrict__ Wl1, int K1,
    const __nv_bfloat16* __restrict__ Ah2, const __nv_bfloat16* __restrict__ Al2,
    const __nv_bfloat16* __restrict__ Wh2, const __nv_bfloat16* __restrict__ Wl2, int K2,
    const float* __restrict__ bias, float* __restrict__ C, int Ntot)
{
    extern __shared__ char smem[];
    const uint32_t sb = smem_u32(smem);
    const int tid = threadIdx.x;
    const int wid = tid >> 5, lane = tid & 31;
    const int wm = wid & 1, wn = wid >> 1;
    const int mt = blockIdx.y, nt = blockIdx.x;
    const int m0 = mt * 128, n0 = nt * 128;
    const int C1 = K1 >> 6, C2 = K2 >> 6;
    const int S = C1 + C2;

    if (tid == 0) {
        MBARRIER_INIT(sb, 1);
        MBARRIER_INIT(sb + 8, 1);
        MBARRIER_INIT(sb + 16, 1);
    }
    __syncthreads();
    if (tid == 0) {
        issue_stage(0, 0, sb, mt, nt, Ah1, Al1, Wh1, Wl1, C1, Ah2, Al2, Wh2, Wl2, C2);
        if (S > 1) issue_stage(1, 1, sb, mt, nt, Ah1, Al1, Wh1, Wl1, C1, Ah2, Al2, Wh2, Wl2, C2);
        if (S > 2) issue_stage(2, 2, sb, mt, nt, Ah1, Al1, Wh1, Wl1, C1, Ah2, Al2, Wh2, Wl2, C2);
    }

    float acc[4][4][4];
    #pragma unroll
    for (int i = 0; i < 4; ++i)
        #pragma unroll
        for (int j = 0; j < 4; ++j)
            #pragma unroll
            for (int k = 0; k < 4; ++k) acc[i][j][k] = 0.f;

    const int tsel = lane >> 3;
    const int trow = lane & 7;
    int ph[3] = {0, 0, 0};

    for (int s = 0; s < S; ++s) {
        const int buf = s % 3;
        MBAR_WAIT(sb + buf * 8, ph[buf]);
        ph[buf] ^= 1;
        const uint32_t Ab  = sb + 1024 + buf * STG;
        const uint32_t Alb = Ab + 16384;
        const uint32_t Wb  = Ab + 32768;
        const uint32_t Wlb = Ab + 49152;

        #pragma unroll
        for (int ks = 0; ks < 4; ++ks) {
            uint32_t ah[4][4], al[4][4], bh[2][4], bl[2][4];
            #pragma unroll
            for (int mi = 0; mi < 4; ++mi) {
                const int row = wm * 64 + mi * 16 + (tsel & 1) * 8 + trow;
                const uint32_t off = row * 128 +
                    (uint32_t)((((ks * 2 + (tsel >> 1)) ^ (row & 7)) << 4));
                ldsm_x4(ah[mi], Ab + off);
                ldsm_x4(al[mi], Alb + off);
            }
            #pragma unroll
            for (int np = 0; np < 2; ++np) {
                const int n = wn * 32 + np * 16 + (tsel >> 1) * 8 + trow;
                const uint32_t off = n * 128 +
                    (uint32_t)((((ks * 2 + (tsel & 1)) ^ (n & 7)) << 4));
                ldsm_x4(bh[np], Wb + off);
                ldsm_x4(bl[np], Wlb + off);
            }
            #pragma unroll
            for (int mi = 0; mi < 4; ++mi)
                #pragma unroll
                for (int ni = 0; ni < 4; ++ni) {
                    const uint32_t h0 = bh[ni >> 1][(ni & 1) * 2];
                    const uint32_t h1 = bh[ni >> 1][(ni & 1) * 2 + 1];
                    const uint32_t l0 = bl[ni >> 1][(ni & 1) * 2];
                    const uint32_t l1 = bl[ni >> 1][(ni & 1) * 2 + 1];
                    mma_bf16(acc[mi][ni], ah[mi], h0, h1);
                    mma_bf16(acc[mi][ni], al[mi], h0, h1);
                    mma_bf16(acc[mi][ni], ah[mi], l0, l1);
                }
        }
        __syncthreads();
        if (tid == 0 && s + 3 < S)
            issue_stage(s + 3, buf, sb, mt, nt, Ah1, Al1, Wh1, Wl1, C1, Ah2, Al2, Wh2, Wl2, C2);
    }

    const int erow = lane >> 2;
    const int ecol = (lane & 3) * 2;
    #pragma unroll
    for (int mi = 0; mi < 4; ++mi) {
        const int r0 = m0 + wm * 64 + mi * 16 + erow;
        #pragma unroll
        for (int ni = 0; ni < 4; ++ni) {
            const int n = n0 + wn * 32 + ni * 8 + ecol;
            float b0 = 0.f, b1 = 0.f;
            if (bias) { b0 = bias[n]; b1 = bias[n + 1]; }
            float2 v0 = make_float2(acc[mi][ni][0] + b0, acc[mi][ni][1] + b1);
            float2 v1 = make_float2(acc[mi][ni][2] + b0, acc[mi][ni][3] + b1);
            *(float2*)(C + (size_t)r0 * Ntot + n)       = v0;
            *(float2*)(C + (size_t)(r0 + 8) * Ntot + n) = v1;
        }
    }
}

// ===================== host driver ==========================================
extern "C" void kernel_launch(void* const* d_in, const int* in_sizes, int n_in,
                              void* d_out, int out_size) {
    int s = (in_sizes[3] <= 16) ? 0 : -1;

    const int*   input_var  = (const int*)  d_in[0];
    const float* input_mask = (const float*)d_in[1];
    const int*   target_var = (const int*)  d_in[2];
    const float* emb      = (const float*)d_in[4 + s];
    const float* attn_w   = (const float*)d_in[5 + s];
    const float* attn_b   = (const float*)d_in[6 + s];
    const float* set_Wih  = (const float*)d_in[7 + s];
    const float* set_Whh  = (const float*)d_in[8 + s];
    const float* set_bih  = (const float*)d_in[9 + s];
    const float* set_bhh  = (const float*)d_in[10 + s];
    const float* set_h0   = (const float*)d_in[11 + s];
    const float* set_c0   = (const float*)d_in[12 + s];
    const float* gen_x0   = (const float*)d_in[13 + s];
    const float* gen_Wih  = (const float*)d_in[14 + s];
    const float* gen_Whh  = (const float*)d_in[15 + s];
    const float* gen_bih  = (const float*)d_in[16 + s];
    const float* gen_bhh  = (const float*)d_in[17 + s];
    const float* gen_outW = (const float*)d_in[18 + s];
    const float* gen_outb = (const float*)d_in[19 + s];
    const float* menc_Wih = (const float*)d_in[20 + s];
    const float* menc_Whh = (const float*)d_in[21 + s];
    const float* menc_bih = (const float*)d_in[22 + s];
    const float* menc_bhh = (const float*)d_in[23 + s];
    const float* menc_h0  = (const float*)d_in[24 + s];
    const float* menc_c0  = (const float*)d_in[25 + s];
    const float* dec_Wih  = (const float*)d_in[26 + s];
    const float* dec_Whh  = (const float*)d_in[27 + s];
    const float* dec_bih  = (const float*)d_in[28 + s];
    const float* dec_bhh  = (const float*)d_in[29 + s];
    const float* dec_outW = (const float*)d_in[30 + s];
    const float* dec_outb = (const float*)d_in[31 + s];
    float* out = (float*)d_out;

    cudaFuncSetAttribute(tc_gemm, cudaFuncAttributeMaxDynamicSharedMemorySize, TC_SMEM_BYTES);

    float *p_g, *p_hb, *p_xb, *p_s0, *p_mmask;
    float *gb_set, *gb_gen, *gb_menc, *gb_dec;
    cudaGetSymbolAddress((void**)&p_g,     g_g);
    cudaGetSymbolAddress((void**)&p_hb,    g_hb_enc);
    cudaGetSymbolAddress((void**)&p_xb,    g_xb_gen);
    cudaGetSymbolAddress((void**)&p_s0,    g_s0);
    cudaGetSymbolAddress((void**)&p_mmask, g_mmask);
    cudaGetSymbolAddress((void**)&gb_set,  g_gb_set);
    cudaGetSymbolAddress((void**)&gb_gen,  g_gb_gen);
    cudaGetSymbolAddress((void**)&gb_menc, g_gb_menc);
    cudaGetSymbolAddress((void**)&gb_dec,  g_gb_dec);

    __nv_bfloat16 *hh, *hl, *rh, *rl, *mh, *ml, *dh, *dl, *hsh, *hsl;
    cudaGetSymbolAddress((void**)&hh, g_h_hi);   cudaGetSymbolAddress((void**)&hl, g_h_lo);
    cudaGetSymbolAddress((void**)&rh, g_r_hi);   cudaGetSymbolAddress((void**)&rl, g_r_lo);
    cudaGetSymbolAddress((void**)&mh, g_msg_hi); cudaGetSymbolAddress((void**)&ml, g_msg_lo);
    cudaGetSymbolAddress((void**)&dh, g_din_hi); cudaGetSymbolAddress((void**)&dl, g_din_lo);
    cudaGetSymbolAddress((void**)&hsh, g_hist_hi); cudaGetSymbolAddress((void**)&hsl, g_hist_lo);

    __nv_bfloat16 *sWih_h, *sWih_l, *gWhh_h, *gWhh_l, *mWih_h, *mWih_l,
                  *mWhh_h, *mWhh_l, *dWih_h, *dWih_l, *dWhh_h, *dWhh_l, *oW_h, *oW_l;
    cudaGetSymbolAddress((void**)&sWih_h, w_setWih_hi);  cudaGetSymbolAddress((void**)&sWih_l, w_setWih_lo);
    cudaGetSymbolAddress((void**)&gWhh_h, w_genWhh_hi);  cudaGetSymbolAddress((void**)&gWhh_l, w_genWhh_lo);
    cudaGetSymbolAddress((void**)&mWih_h, w_mencWih_hi); cudaGetSymbolAddress((void**)&mWih_l, w_mencWih_lo);
    cudaGetSymbolAddress((void**)&mWhh_h, w_mencWhh_hi); cudaGetSymbolAddress((void**)&mWhh_l, w_mencWhh_lo);
    cudaGetSymbolAddress((void**)&dWih_h, w_decWih_hi);  cudaGetSymbolAddress((void**)&dWih_l, w_decWih_lo);
    cudaGetSymbolAddress((void**)&dWhh_h, w_decWhh_hi);  cudaGetSymbolAddress((void**)&dWhh_l, w_decWhh_lo);
    cudaGetSymbolAddress((void**)&oW_h,   w_outW_hi);    cudaGetSymbolAddress((void**)&oW_l,   w_outW_lo);

    const dim3 gBig(H4z / 128, Bz / 128);       // (32, 4) gate GEMMs
    const dim3 gFin(Vz / 128, (Tz * Bz) / 128); // (8, 200) batched out projection
    const int SPLIT_T = 256;
    const int BC_B = (Bz * Hz + 255) / 256;

    // ---- weight splits (gate-interleaved for recurrent mats) ----
    split_w_blk_gate_kernel<<<(H4z * Hz + SPLIT_T - 1) / SPLIT_T, SPLIT_T>>>(set_Wih,  sWih_h, sWih_l, Hz,  H4z * Hz);
    split_w_blk_gate_kernel<<<(H4z * Hz + SPLIT_T - 1) / SPLIT_T, SPLIT_T>>>(gen_Whh,  gWhh_h, gWhh_l, Hz,  H4z * Hz);
    split_w_blk_gate_kernel<<<(H4z * MVz + SPLIT_T - 1) / SPLIT_T, SPLIT_T>>>(menc_Wih, mWih_h, mWih_l, MVz, H4z * MVz);
    split_w_blk_gate_kernel<<<(H4z * Hz + SPLIT_T - 1) / SPLIT_T, SPLIT_T>>>(menc_Whh, mWhh_h, mWhh_l, Hz,  H4z * Hz);
    split_w_blk_gate_kernel<<<(H4z * Hz + SPLIT_T - 1) / SPLIT_T, SPLIT_T>>>(dec_Wih,  dWih_h, dWih_l, Hz,  H4z * Hz);
    split_w_blk_gate_kernel<<<(H4z * Hz + SPLIT_T - 1) / SPLIT_T, SPLIT_T>>>(dec_Whh,  dWhh_h, dWhh_l, Hz,  H4z * Hz);
    split_w_blk_kernel<<<(Vz * Hz + SPLIT_T - 1) / SPLIT_T, SPLIT_T>>>(dec_outW, oW_h, oW_l, Hz, Vz * Hz);

    // ---- precompute ----
    vecmat_kernel<<<1, 32>>>(set_h0, attn_w, p_s0, 1, Hz);
    vecmat_kernel<<<H4z / 8, 256>>>(set_h0, set_Whh, p_hb, H4z, Hz);
    vecmat_kernel<<<H4z / 8, 256>>>(gen_x0, gen_Wih, p_xb, H4z, MVz);
    bias4_kernel<<<H4z / 256, 256>>>(set_bih,  set_bhh,  p_hb,    gb_set);
    bias4_kernel<<<H4z / 256, 256>>>(gen_bih,  gen_bhh,  p_xb,    gb_gen);
    bias4_kernel<<<H4z / 256, 256>>>(menc_bih, menc_bhh, nullptr, gb_menc);
    bias4_kernel<<<H4z / 256, 256>>>(dec_bih,  dec_bhh,  nullptr, gb_dec);
    attn_aw_kernel<<<(Bz * Wz + 7) / 8, 256>>>(input_var, input_mask, emb, attn_w, attn_b);
    attn_r_kernel<<<Bz, 256>>>(input_var, emb);
    dec_gather_kernel<<<(int)(((size_t)Tz * Bz * Hz + 255) / 256), 256>>>(target_var, emb);
    init_m_kernel<<<2, 256>>>();

    // ---- set encoder (A1 = r; h0@Whh folded into gb_set) ----
    bcast_BH_kernel<<<BC_B, 256>>>(set_c0, 1);
    tc_gemm<<<gBig, 256, TC_SMEM_BYTES>>>(rh, rl, sWih_h, sWih_l, Hz,
                                          nullptr, nullptr, nullptr, nullptr, 0,
                                          nullptr, p_g, H4z);
    lstm_gate4_kernel<<<BC_B, 256>>>(gb_set, nullptr, nullptr, nullptr, 0);

    // ---- generator loop (fused gate + softmax head) ----
    for (int t = 0; t < Lz; ++t) {
        tc_gemm<<<gBig, 256, TC_SMEM_BYTES>>>(hh, hl, gWhh_h, gWhh_l, Hz,
                                              nullptr, nullptr, nullptr, nullptr, 0,
                                              nullptr, p_g, H4z);
        gen_gate_out_kernel<<<Bz, 256>>>(gb_gen, gen_outW, gen_outb, t);
    }

    // ---- message encoder loop ----
    bcast_BH_kernel<<<BC_B, 256>>>(menc_h0, 0);
    bcast_BH_kernel<<<BC_B, 256>>>(menc_c0, 1);
    for (int t = 0; t < Lz; ++t) {
        tc_gemm<<<gBig, 256, TC_SMEM_BYTES>>>(mh + (size_t)t * Bz * MVz, ml + (size_t)t * Bz * MVz,
                                              mWih_h, mWih_l, MVz,
                                              hh, hl, mWhh_h, mWhh_l, Hz,
                                              nullptr, p_g, H4z);
        lstm_gate4_kernel<<<BC_B, 256>>>(gb_menc, p_mmask + (size_t)t * Bz, nullptr, nullptr, 0);
    }

    // ---- decoder loop (gate writes history slice; out-proj deferred) ----
    for (int t = 0; t < Tz; ++t) {
        const __nv_bfloat16* a2h = (t == 0) ? hh : hsh + (size_t)(t - 1) * Bz * Hz;
        const __nv_bfloat16* a2l = (t == 0) ? hl : hsl + (size_t)(t - 1) * Bz * Hz;
        tc_gemm<<<gBig, 256, TC_SMEM_BYTES>>>(dh + (size_t)t * Bz * Hz, dl + (size_t)t * Bz * Hz,
                                              dWih_h, dWih_l, Hz,
                                              a2h, a2l, dWhh_h, dWhh_l, Hz,
                                              nullptr, p_g, H4z);
        lstm_gate4_kernel<<<BC_B, 256>>>(gb_dec, nullptr, hsh, hsl, t * Bz);
    }

    // ---- deferred batched output projection ----
    tc_gemm<<<gFin, 256, TC_SMEM_BYTES>>>(hsh, hsl, oW_h, oW_l, Hz,
                                          nullptr, nullptr, nullptr, nullptr, 0,
                                          dec_outb, out, Vz);
    (void)n_in; (void)out_size;
}